// round 14
// baseline (speedup 1.0000x reference)
#include <cuda_runtime.h>
#include <math.h>
#include <stdint.h>

// Problem constants
#define Bq   2
#define Pq   4000
#define NPq  4096
#define Mq   512
#define HWq  214272            // 496 * 432

// Output section offsets (in floats)
static constexpr long O1 = (long)Bq * 128 * HWq;          // spatial_features_point
static constexpr long O2 = 2 * O1;                        // spatial_scale_features
static constexpr long O3 = O2 + (long)Bq * 64 * HWq;      // point_positive_features
static constexpr long O4 = O3 + (long)Bq * Pq * 64;       // memory_positive_features

static constexpr long N4ALL = O3 / 4;                     // float4s to zero

// Winner map for duplicate-index resolution (last-write-wins => max pillar idx)
__device__ int g_winner[Bq * HWq];

__global__ void winner_reset_kernel() {
    int i = blockIdx.x * blockDim.x + threadIdx.x;
    if (i < Bq * HWq) g_winner[i] = -1;
}

__global__ void winner_mark_kernel(const int* __restrict__ idxs) {
    int i = blockIdx.x * blockDim.x + threadIdx.x;
    if (i < Bq * Pq) {
        int b = i / Pq;
        int p = i - b * Pq;
        atomicMax(&g_winner[b * HWq + idxs[i]], p);
    }
}

// Dedicated zero-fill kernel (runs CONCURRENTLY with the topk kernels on a
// forked capture stream; drains at DRAM rate without touching their LSU).
__global__ void zero_kernel(float4* __restrict__ out, long n4) {
    long i = (long)blockIdx.x * blockDim.x + threadIdx.x;
    long stride = (long)gridDim.x * blockDim.x;
    float4 z = make_float4(0.f, 0.f, 0.f, 0.f);
    for (; i < n4; i += stride) out[i] = z;
}

// ---------------------------------------------------------------------------
// Packed f32x2 helpers (Blackwell) + cp.async
// ---------------------------------------------------------------------------
__device__ __forceinline__ void ffma2(unsigned long long& d,
                                      unsigned long long a,
                                      unsigned long long b) {
    asm("fma.rn.f32x2 %0, %1, %2, %0;" : "+l"(d) : "l"(a), "l"(b));
}
__device__ __forceinline__ unsigned long long pack2(float a, float b) {
    unsigned long long r;
    asm("mov.b64 %0, {%1, %2};" : "=l"(r) : "f"(a), "f"(b));
    return r;
}
__device__ __forceinline__ float pairsum(unsigned long long u) {
    float lo, hi;
    asm("mov.b64 {%0, %1}, %2;" : "=f"(lo), "=f"(hi) : "l"(u));
    return lo + hi;
}
__device__ __forceinline__ uint32_t smem_u32(const void* p) {
    uint32_t a;
    asm("{ .reg .u64 t; cvta.to.shared.u64 t, %1; cvt.u32.u64 %0, t; }" : "=r"(a) : "l"(p));
    return a;
}
__device__ __forceinline__ void cp_async16(uint32_t saddr, const void* gptr) {
    asm volatile("cp.async.cg.shared.global [%0], [%1], 16;" :: "r"(saddr), "l"(gptr));
}
__device__ __forceinline__ void cp_commit() {
    asm volatile("cp.async.commit_group;");
}
template<int N>
__device__ __forceinline__ void cp_wait() {
    asm volatile("cp.async.wait_group %0;" :: "n"(N));
}

// Fully-unrolled top-8 insertion (registers only; sorted descending)
__device__ __forceinline__ void top8_insert(float (&tv)[8], int (&ti)[8], float v, int n) {
    if (v > tv[7]) {
#pragma unroll
        for (int s = 0; s < 8; ++s) {
            if (v > tv[s]) {
                float a = tv[s]; int b = ti[s];
                tv[s] = v; ti[s] = n;
                v = a; n = b;
            }
        }
    }
}

// ---------------------------------------------------------------------------
// Register-stationary fused GEMM + top-8 + softmax + gather, cp.async
// double-buffered X tiles, two-row-interleaved FFMA2 chains. (Zero-fill now
// lives in a concurrent kernel — this one keeps its LSU for LDS/cp.async.)
//
// Block: 256 threads (8 warps), 32 pillars. Lane l owns pillar pBase+l fully
// in registers (32 f32x2 pairs). Tile = 128 X rows; warp w computes rows
// [16w, 16w+16) via broadcast smem reads while the next tile streams in.
// ---------------------------------------------------------------------------
#define SMEM_BYTES 65536   // 2 x (128*64 floats); merge phase reuses buffer 0

template<int NROWTILES>   // N / 128
__global__ __launch_bounds__(256, 2) void topk_warp_kernel(
    const float* __restrict__ pillars,  // [B, P, 64]
    const float* __restrict__ X,        // [B, N, 64] or [N, 64] (xStride = 0)
    float* __restrict__ outp,           // [B, P, 64]
    int xStride)
{
    extern __shared__ float smem[];

    const int b = blockIdx.y;
    const int pBase = blockIdx.x * 32;
    const float* pil = pillars + (size_t)b * Pq * 64;
    const float* Xb  = X + (size_t)b * xStride;
    float* outb = outp + (size_t)b * Pq * 64;

    const int tid  = threadIdx.x;
    const int lane = tid & 31;
    const int warp = tid >> 5;

    // Lane-private pillar row in registers as 32 f32x2 pairs
    unsigned long long pk[32];
    {
        const float4* prow = (const float4*)(pil + (size_t)(pBase + lane) * 64);
#pragma unroll
        for (int i = 0; i < 16; i++) {
            float4 f = prow[i];
            pk[2 * i]     = pack2(f.x, f.y);
            pk[2 * i + 1] = pack2(f.z, f.w);
        }
    }

    float topv[8]; int topi[8];
#pragma unroll
    for (int s = 0; s < 8; s++) { topv[s] = -INFINITY; topi[s] = 0; }

    // cp.async staging: thread t copies float4 elements {t, t+256, ..., t+1792}
    const uint32_t sbuf0 = smem_u32(smem);
    const uint32_t sbuf1 = sbuf0 + 32768;

    // Prologue: stage tile 0 into buffer 0
    {
        const float4* xsrc = (const float4*)Xb;
#pragma unroll
        for (int i = 0; i < 8; i++)
            cp_async16(sbuf0 + 16 * (tid + 256 * i), xsrc + tid + 256 * i);
        cp_commit();
    }

    for (int tile = 0; tile < NROWTILES; tile++) {
        // Stage next tile into the other buffer, then wait for current tile
        if (tile + 1 < NROWTILES) {
            const float4* xsrc = (const float4*)Xb + (size_t)(tile + 1) * (128 * 16);
            uint32_t dst = ((tile + 1) & 1) ? sbuf1 : sbuf0;
#pragma unroll
            for (int i = 0; i < 8; i++)
                cp_async16(dst + 16 * (tid + 256 * i), xsrc + tid + 256 * i);
            cp_commit();
            cp_wait<1>();
        } else {
            cp_wait<0>();
        }
        __syncthreads();

        // Warp w processes rows [16w, 16w+16) of this tile; broadcast reads.
        const float* buf = ((tile & 1) ? (smem + 8192) : smem);
        const ulonglong2* xrow = (const ulonglong2*)(buf + warp * (16 * 64));
        const int nbase = tile * 128 + warp * 16;
#pragma unroll 2
        for (int r = 0; r < 16; r += 2) {
            unsigned long long a0 = 0ull, a1 = 0ull, b0 = 0ull, b1 = 0ull;
            const ulonglong2* xr0 = xrow + r * 16;
            const ulonglong2* xr1 = xr0 + 16;
#pragma unroll
            for (int k8 = 0; k8 < 16; k8++) {
                ulonglong2 x0 = xr0[k8];
                ulonglong2 x1 = xr1[k8];
                ffma2(a0, pk[2 * k8],     x0.x);
                ffma2(a1, pk[2 * k8 + 1], x0.y);
                ffma2(b0, pk[2 * k8],     x1.x);
                ffma2(b1, pk[2 * k8 + 1], x1.y);
            }
            float v0 = pairsum(a0) + pairsum(a1);
            float v1 = pairsum(b0) + pairsum(b1);
            top8_insert(topv, topi, v0, nbase + r);
            top8_insert(topv, topi, v1, nbase + r + 1);
        }
        __syncthreads();   // all warps done reading buf before it is re-staged
    }

    // ---- merge phase (reuse smem) ----
    float* candV = smem;                         // [32][65] padded
    int*   candI = (int*)(smem + 32 * 65);       // [32][65]
    float* wV    = smem + 2 * 32 * 65;           // [32][8]
    int*   wI    = (int*)(smem + 2 * 32 * 65 + 32 * 8);

#pragma unroll
    for (int s = 0; s < 8; s++) {
        candV[lane * 65 + warp * 8 + s] = topv[s];
        candI[lane * 65 + warp * 8 + s] = topi[s];
    }
    __syncthreads();

    // One thread per pillar merges 64 candidates -> final top-8 -> softmax
    if (tid < 32) {
        int m = tid;
        float fv[8]; int fi[8];
#pragma unroll
        for (int s = 0; s < 8; s++) { fv[s] = -INFINITY; fi[s] = 0; }
        for (int c = 0; c < 64; c++)
            top8_insert(fv, fi, candV[m * 65 + c], candI[m * 65 + c]);
        float w[8]; float sum = 0.f;
#pragma unroll
        for (int s = 0; s < 8; s++) { w[s] = expf(fv[s] - fv[0]); sum += w[s]; }
        float inv = 1.f / sum;
#pragma unroll
        for (int s = 0; s < 8; s++) { wV[m * 8 + s] = w[s] * inv; wI[m * 8 + s] = fi[s]; }
    }
    __syncthreads();

    // Weighted gather: out[p][d] = sum_k w_k * X[idx_k][d]  (rows are L2-hot)
#pragma unroll
    for (int i = 0; i < 8; i++) {
        int lin = tid + 256 * i;
        int m = lin >> 6, d = lin & 63;
        float s = 0.f;
#pragma unroll
        for (int kk = 0; kk < 8; kk++)
            s += wV[m * 8 + kk] * Xb[(size_t)wI[m * 8 + kk] * 64 + d];
        outb[(size_t)(pBase + m) * 64 + d] = s;
    }
}

// ---------------------------------------------------------------------------
// Scatter: winner pillar per BEV column writes the three dense grids.
// ---------------------------------------------------------------------------
__global__ __launch_bounds__(64) void scatter_kernel(
    const float* __restrict__ pillars, const float* __restrict__ scales,
    const float* __restrict__ posP,    const float* __restrict__ posM,
    const int* __restrict__ idxs,      float* __restrict__ out)
{
    int bp = blockIdx.x;
    int b = bp / Pq, p = bp - b * Pq;
    int col = idxs[bp];
    if (g_winner[b * HWq + col] != p) return;
    int d = threadIdx.x;

    size_t o = (size_t)bp * 64 + d;
    float pilv = pillars[o];
    float scv  = scales[o];
    float ppv  = posP[o];
    float pmv  = posM[o];

    float* sp  = out;               // spatial_features       [B,128,HW]: [pillars ; pos_mem]
    float* spp = out + (size_t)O1;  // spatial_features_point [B,128,HW]: [pillars ; pos_point]
    float* sps = out + (size_t)O2;  // spatial_scale_features [B, 64,HW]

    size_t base = (size_t)b * 128 * HWq + (size_t)d * HWq + col;
    sp [base] = pilv;
    sp [base + (size_t)64 * HWq] = pmv;
    spp[base] = pilv;
    spp[base + (size_t)64 * HWq] = ppv;
    sps[(size_t)b * 64 * HWq + (size_t)d * HWq + col] = scv;
}

// ---------------------------------------------------------------------------
// Side-stream resources: created once on the FIRST call (the correctness run,
// which is not graph-captured). No device memory is allocated. Every call
// performs identical launches; the fork/join events become graph dependencies
// during capture, making zero-fill + winner kernels run concurrently with the
// topk kernels.
// ---------------------------------------------------------------------------
struct SideRes {
    cudaStream_t s2;
    cudaEvent_t  eFork, eJoin;
    SideRes() {
        cudaStreamCreateWithFlags(&s2, cudaStreamNonBlocking);
        cudaEventCreateWithFlags(&eFork, cudaEventDisableTiming);
        cudaEventCreateWithFlags(&eJoin, cudaEventDisableTiming);
    }
};
static SideRes& side() { static SideRes r; return r; }

extern "C" void kernel_launch(void* const* d_in, const int* in_sizes, int n_in,
                              void* d_out, int out_size) {
    (void)in_sizes; (void)n_in; (void)out_size;
    const float* pillars = (const float*)d_in[0];   // [B,P,64]
    const float* scales  = (const float*)d_in[1];   // [B,P,64]
    const float* points  = (const float*)d_in[2];   // [B,NP,64]
    const float* W       = (const float*)d_in[3];   // [M,64]
    const int*   idxs    = (const int*)d_in[4];     // [B,P]
    float* out = (float*)d_out;

    SideRes& R = side();

    cudaFuncSetAttribute(topk_warp_kernel<NPq / 128>,
                         cudaFuncAttributeMaxDynamicSharedMemorySize, SMEM_BYTES);
    cudaFuncSetAttribute(topk_warp_kernel<Mq / 128>,
                         cudaFuncAttributeMaxDynamicSharedMemorySize, SMEM_BYTES);

    // Fork the side branch off the main (capture) stream.
    cudaEventRecord(R.eFork, 0);
    cudaStreamWaitEvent(R.s2, R.eFork, 0);

    // Side branch: zero-fill the dense spatial region + winner resolution.
    zero_kernel<<<8192, 256, 0, R.s2>>>((float4*)out, N4ALL);
    winner_reset_kernel<<<(Bq * HWq + 255) / 256, 256, 0, R.s2>>>();
    winner_mark_kernel<<<(Bq * Pq + 255) / 256, 256, 0, R.s2>>>(idxs);
    cudaEventRecord(R.eJoin, R.s2);

    // Main stream: the two fused attention stages (concurrent with the fill).
    dim3 grid(Pq / 32, Bq);   // 125 x 2 = 250 blocks
    topk_warp_kernel<NPq / 128><<<grid, 256, SMEM_BYTES>>>(
        pillars, points, out + O3, NPq * 64);
    topk_warp_kernel<Mq / 128><<<grid, 256, SMEM_BYTES>>>(
        pillars, W,      out + O4, 0);

    // Join: scatter needs zeroed grids, winner map, and both topk outputs.
    cudaStreamWaitEvent(0, R.eJoin, 0);
    scatter_kernel<<<Bq * Pq, 64>>>(pillars, scales, out + O3, out + O4, idxs, out);
}

// round 15
// speedup vs baseline: 1.0757x; 1.0757x over previous
#include <cuda_runtime.h>
#include <math.h>
#include <stdint.h>

// Problem constants
#define Bq   2
#define Pq   4000
#define NPq  4096
#define Mq   512
#define HWq  214272            // 496 * 432

// Output section offsets (in floats)
static constexpr long O1 = (long)Bq * 128 * HWq;          // spatial_features_point
static constexpr long O2 = 2 * O1;                        // spatial_scale_features
static constexpr long O3 = O2 + (long)Bq * 64 * HWq;      // point_positive_features
static constexpr long O4 = O3 + (long)Bq * Pq * 64;       // memory_positive_features

static constexpr long N4ALL = O3 / 4;                     // float4s to zero

// Winner map for duplicate-index resolution (last-write-wins => max pillar idx)
__device__ int g_winner[Bq * HWq];

__global__ void winner_reset_kernel() {
    int i = blockIdx.x * blockDim.x + threadIdx.x;
    if (i < Bq * HWq) g_winner[i] = -1;
}

__global__ void winner_mark_kernel(const int* __restrict__ idxs) {
    int i = blockIdx.x * blockDim.x + threadIdx.x;
    if (i < Bq * Pq) {
        int b = i / Pq;
        int p = i - b * Pq;
        atomicMax(&g_winner[b * HWq + idxs[i]], p);
    }
}

// Dedicated zero-fill kernel (runs SERIALLY after the topk kernels: measured
// evidence shows concurrent fill saturates LTS/DRAM and slows topk ~1.5x,
// costing more than it hides).
__global__ void zero_kernel(float4* __restrict__ out, long n4) {
    long i = (long)blockIdx.x * blockDim.x + threadIdx.x;
    long stride = (long)gridDim.x * blockDim.x;
    float4 z = make_float4(0.f, 0.f, 0.f, 0.f);
    for (; i < n4; i += stride) out[i] = z;
}

// ---------------------------------------------------------------------------
// Packed f32x2 helpers (Blackwell) + cp.async
// ---------------------------------------------------------------------------
__device__ __forceinline__ void ffma2(unsigned long long& d,
                                      unsigned long long a,
                                      unsigned long long b) {
    asm("fma.rn.f32x2 %0, %1, %2, %0;" : "+l"(d) : "l"(a), "l"(b));
}
__device__ __forceinline__ unsigned long long pack2(float a, float b) {
    unsigned long long r;
    asm("mov.b64 %0, {%1, %2};" : "=l"(r) : "f"(a), "f"(b));
    return r;
}
__device__ __forceinline__ float pairsum(unsigned long long u) {
    float lo, hi;
    asm("mov.b64 {%0, %1}, %2;" : "=f"(lo), "=f"(hi) : "l"(u));
    return lo + hi;
}
__device__ __forceinline__ uint32_t smem_u32(const void* p) {
    uint32_t a;
    asm("{ .reg .u64 t; cvta.to.shared.u64 t, %1; cvt.u32.u64 %0, t; }" : "=r"(a) : "l"(p));
    return a;
}
__device__ __forceinline__ void cp_async16(uint32_t saddr, const void* gptr) {
    asm volatile("cp.async.cg.shared.global [%0], [%1], 16;" :: "r"(saddr), "l"(gptr));
}
__device__ __forceinline__ void cp_commit() {
    asm volatile("cp.async.commit_group;");
}
template<int N>
__device__ __forceinline__ void cp_wait() {
    asm volatile("cp.async.wait_group %0;" :: "n"(N));
}

// Fully-unrolled top-8 insertion (registers only; sorted descending)
__device__ __forceinline__ void top8_insert(float (&tv)[8], int (&ti)[8], float v, int n) {
    if (v > tv[7]) {
#pragma unroll
        for (int s = 0; s < 8; ++s) {
            if (v > tv[s]) {
                float a = tv[s]; int b = ti[s];
                tv[s] = v; ti[s] = n;
                v = a; n = b;
            }
        }
    }
}

// ---------------------------------------------------------------------------
// Register-stationary fused GEMM + top-8 + softmax + gather with PER-WARP
// cp.async double-buffered row slices (no block barriers in the mainloop —
// the tile data is warp-private, so warps run fully decoupled).
//
// Block: 256 threads (8 warps), 32 pillars. Lane l owns pillar pBase+l fully
// in registers (32 f32x2 pairs). Per tile of 128 rows, warp w owns rows
// [16w, 16w+16): its lanes cp.async that 4KB slice into one of two private
// smem buffers, wait_group + __syncwarp, then broadcast-read and FFMA2.
// ---------------------------------------------------------------------------
#define SMEM_BYTES 65536   // 8 warps x 2 buffers x 4KB; merge phase reuses it

template<int NROWTILES>   // N / 128
__global__ __launch_bounds__(256, 2) void topk_warp_kernel(
    const float* __restrict__ pillars,  // [B, P, 64]
    const float* __restrict__ X,        // [B, N, 64] or [N, 64] (xStride = 0)
    float* __restrict__ outp,           // [B, P, 64]
    int xStride)
{
    extern __shared__ float smem[];

    const int b = blockIdx.y;
    const int pBase = blockIdx.x * 32;
    const float* pil = pillars + (size_t)b * Pq * 64;
    const float* Xb  = X + (size_t)b * xStride;
    float* outb = outp + (size_t)b * Pq * 64;

    const int tid  = threadIdx.x;
    const int lane = tid & 31;
    const int warp = tid >> 5;

    // Lane-private pillar row in registers as 32 f32x2 pairs
    unsigned long long pk[32];
    {
        const float4* prow = (const float4*)(pil + (size_t)(pBase + lane) * 64);
#pragma unroll
        for (int i = 0; i < 16; i++) {
            float4 f = prow[i];
            pk[2 * i]     = pack2(f.x, f.y);
            pk[2 * i + 1] = pack2(f.z, f.w);
        }
    }

    float topv[8]; int topi[8];
#pragma unroll
    for (int s = 0; s < 8; s++) { topv[s] = -INFINITY; topi[s] = 0; }

    // Per-warp double buffers: warp w owns smem bytes [w*8192, w*8192+8192)
    const uint32_t wbufB = smem_u32(smem) + warp * 8192;   // byte address
    float* wbufF = smem + warp * 2048;                     // float pointer

    // Stage warp slice of tile t into buffer (t&1):
    //   rows t*128 + 16w .. +16 (4KB = 256 float4; lane copies 8 of them)
    auto stage = [&](int t) {
        const float4* g = (const float4*)Xb + ((size_t)t * 128 + warp * 16) * 16;
        uint32_t dst = wbufB + (t & 1) * 4096;
#pragma unroll
        for (int i = 0; i < 8; i++)
            cp_async16(dst + 16 * (lane + 32 * i), g + lane + 32 * i);
        cp_commit();
    };

    stage(0);

    for (int tile = 0; tile < NROWTILES; tile++) {
        if (tile + 1 < NROWTILES) { stage(tile + 1); cp_wait<1>(); }
        else                      { cp_wait<0>(); }
        __syncwarp();   // all lanes' async copies for this tile are visible

        const float* buf = wbufF + (tile & 1) * 1024;
        const ulonglong2* xrow = (const ulonglong2*)buf;
        const int nbase = tile * 128 + warp * 16;
#pragma unroll 2
        for (int r = 0; r < 16; r += 2) {
            unsigned long long a0 = 0ull, a1 = 0ull, b0 = 0ull, b1 = 0ull;
            const ulonglong2* xr0 = xrow + r * 16;
            const ulonglong2* xr1 = xr0 + 16;
#pragma unroll
            for (int k8 = 0; k8 < 16; k8++) {
                ulonglong2 x0 = xr0[k8];
                ulonglong2 x1 = xr1[k8];
                ffma2(a0, pk[2 * k8],     x0.x);
                ffma2(a1, pk[2 * k8 + 1], x0.y);
                ffma2(b0, pk[2 * k8],     x1.x);
                ffma2(b1, pk[2 * k8 + 1], x1.y);
            }
            float v0 = pairsum(a0) + pairsum(a1);
            float v1 = pairsum(b0) + pairsum(b1);
            top8_insert(topv, topi, v0, nbase + r);
            top8_insert(topv, topi, v1, nbase + r + 1);
        }
        __syncwarp();   // lanes done reading before this buffer is re-staged
    }

    // ---- merge phase (block-wide; reuses smem, so barrier first) ----
    __syncthreads();
    float* candV = smem;                         // [32][65] padded
    int*   candI = (int*)(smem + 32 * 65);       // [32][65]
    float* wV    = smem + 2 * 32 * 65;           // [32][8]
    int*   wI    = (int*)(smem + 2 * 32 * 65 + 32 * 8);

#pragma unroll
    for (int s = 0; s < 8; s++) {
        candV[lane * 65 + warp * 8 + s] = topv[s];
        candI[lane * 65 + warp * 8 + s] = topi[s];
    }
    __syncthreads();

    // One thread per pillar merges 64 candidates -> final top-8 -> softmax
    if (tid < 32) {
        int m = tid;
        float fv[8]; int fi[8];
#pragma unroll
        for (int s = 0; s < 8; s++) { fv[s] = -INFINITY; fi[s] = 0; }
        for (int c = 0; c < 64; c++)
            top8_insert(fv, fi, candV[m * 65 + c], candI[m * 65 + c]);
        float w[8]; float sum = 0.f;
#pragma unroll
        for (int s = 0; s < 8; s++) { w[s] = expf(fv[s] - fv[0]); sum += w[s]; }
        float inv = 1.f / sum;
#pragma unroll
        for (int s = 0; s < 8; s++) { wV[m * 8 + s] = w[s] * inv; wI[m * 8 + s] = fi[s]; }
    }
    __syncthreads();

    // Weighted gather: out[p][d] = sum_k w_k * X[idx_k][d]  (rows are L2-hot)
#pragma unroll
    for (int i = 0; i < 8; i++) {
        int lin = tid + 256 * i;
        int m = lin >> 6, d = lin & 63;
        float s = 0.f;
#pragma unroll
        for (int kk = 0; kk < 8; kk++)
            s += wV[m * 8 + kk] * Xb[(size_t)wI[m * 8 + kk] * 64 + d];
        outb[(size_t)(pBase + m) * 64 + d] = s;
    }
}

// ---------------------------------------------------------------------------
// Scatter: winner pillar per BEV column writes the three dense grids.
// ---------------------------------------------------------------------------
__global__ __launch_bounds__(64) void scatter_kernel(
    const float* __restrict__ pillars, const float* __restrict__ scales,
    const float* __restrict__ posP,    const float* __restrict__ posM,
    const int* __restrict__ idxs,      float* __restrict__ out)
{
    int bp = blockIdx.x;
    int b = bp / Pq, p = bp - b * Pq;
    int col = idxs[bp];
    if (g_winner[b * HWq + col] != p) return;
    int d = threadIdx.x;

    size_t o = (size_t)bp * 64 + d;
    float pilv = pillars[o];
    float scv  = scales[o];
    float ppv  = posP[o];
    float pmv  = posM[o];

    float* sp  = out;               // spatial_features       [B,128,HW]: [pillars ; pos_mem]
    float* spp = out + (size_t)O1;  // spatial_features_point [B,128,HW]: [pillars ; pos_point]
    float* sps = out + (size_t)O2;  // spatial_scale_features [B, 64,HW]

    size_t base = (size_t)b * 128 * HWq + (size_t)d * HWq + col;
    sp [base] = pilv;
    sp [base + (size_t)64 * HWq] = pmv;
    spp[base] = pilv;
    spp[base + (size_t)64 * HWq] = ppv;
    sps[(size_t)b * 64 * HWq + (size_t)d * HWq + col] = scv;
}

// ---------------------------------------------------------------------------
extern "C" void kernel_launch(void* const* d_in, const int* in_sizes, int n_in,
                              void* d_out, int out_size) {
    (void)in_sizes; (void)n_in; (void)out_size;
    const float* pillars = (const float*)d_in[0];   // [B,P,64]
    const float* scales  = (const float*)d_in[1];   // [B,P,64]
    const float* points  = (const float*)d_in[2];   // [B,NP,64]
    const float* W       = (const float*)d_in[3];   // [M,64]
    const int*   idxs    = (const int*)d_in[4];     // [B,P]
    float* out = (float*)d_out;

    cudaFuncSetAttribute(topk_warp_kernel<NPq / 128>,
                         cudaFuncAttributeMaxDynamicSharedMemorySize, SMEM_BYTES);
    cudaFuncSetAttribute(topk_warp_kernel<Mq / 128>,
                         cudaFuncAttributeMaxDynamicSharedMemorySize, SMEM_BYTES);

    // Serial single-stream schedule (measured: concurrent fill slows topk
    // more than the overlap saves).
    winner_reset_kernel<<<(Bq * HWq + 255) / 256, 256>>>();
    winner_mark_kernel<<<(Bq * Pq + 255) / 256, 256>>>(idxs);

    dim3 grid(Pq / 32, Bq);   // 125 x 2 = 250 blocks
    topk_warp_kernel<NPq / 128><<<grid, 256, SMEM_BYTES>>>(
        pillars, points, out + O3, NPq * 64);
    topk_warp_kernel<Mq / 128><<<grid, 256, SMEM_BYTES>>>(
        pillars, W,      out + O4, 0);

    zero_kernel<<<8192, 256>>>((float4*)out, N4ALL);

    scatter_kernel<<<Bq * Pq, 64>>>(pillars, scales, out + O3, out + O4, idxs, out);
}

// round 16
// speedup vs baseline: 1.1931x; 1.1092x over previous
#include <cuda_runtime.h>
#include <math.h>
#include <stdint.h>

// Problem constants
#define Bq   2
#define Pq   4000
#define NPq  4096
#define Mq   512
#define HWq  214272            // 496 * 432

// Output section offsets (in floats)
static constexpr long O1 = (long)Bq * 128 * HWq;          // spatial_features_point
static constexpr long O2 = 2 * O1;                        // spatial_scale_features
static constexpr long O3 = O2 + (long)Bq * 64 * HWq;      // point_positive_features
static constexpr long O4 = O3 + (long)Bq * Pq * 64;       // memory_positive_features

// Zero-fill via TMA bulk copies: region [0, O3) floats = 548,536,320 bytes.
static constexpr long FILL_BYTES  = O3 * 4;
static constexpr long CHUNK       = 8192;                  // bulk copy size
static constexpr long NCHUNKS     = FILL_BYTES / CHUNK;    // 66960 exactly
static constexpr int  NBLOCKS     = 250;
static constexpr long CH_PER_BLK  = (NCHUNKS + NBLOCKS - 1) / NBLOCKS;  // 268
static constexpr int  NTICKS      = 36;                    // 4 (W) + 32 (points)
static constexpr long CH_PER_TICK = (CH_PER_BLK + NTICKS - 1) / NTICKS; // 8

// Winner map for duplicate-index resolution (last-write-wins => max pillar idx)
__device__ int g_winner[Bq * HWq];

__global__ void winner_reset_kernel() {
    int i = blockIdx.x * blockDim.x + threadIdx.x;
    if (i < Bq * HWq) g_winner[i] = -1;
}

__global__ void winner_mark_kernel(const int* __restrict__ idxs) {
    int i = blockIdx.x * blockDim.x + threadIdx.x;
    if (i < Bq * Pq) {
        int b = i / Pq;
        int p = i - b * Pq;
        atomicMax(&g_winner[b * HWq + idxs[i]], p);
    }
}

// ---------------------------------------------------------------------------
// Packed f32x2 helpers (Blackwell) + cp.async + bulk-copy
// ---------------------------------------------------------------------------
__device__ __forceinline__ void ffma2(unsigned long long& d,
                                      unsigned long long a,
                                      unsigned long long b) {
    asm("fma.rn.f32x2 %0, %1, %2, %0;" : "+l"(d) : "l"(a), "l"(b));
}
__device__ __forceinline__ unsigned long long pack2(float a, float b) {
    unsigned long long r;
    asm("mov.b64 %0, {%1, %2};" : "=l"(r) : "f"(a), "f"(b));
    return r;
}
__device__ __forceinline__ float pairsum(unsigned long long u) {
    float lo, hi;
    asm("mov.b64 {%0, %1}, %2;" : "=f"(lo), "=f"(hi) : "l"(u));
    return lo + hi;
}
__device__ __forceinline__ uint32_t smem_u32(const void* p) {
    uint32_t a;
    asm("{ .reg .u64 t; cvta.to.shared.u64 t, %1; cvt.u32.u64 %0, t; }" : "=r"(a) : "l"(p));
    return a;
}
__device__ __forceinline__ void cp_async16(uint32_t saddr, const void* gptr) {
    asm volatile("cp.async.cg.shared.global [%0], [%1], 16;" :: "r"(saddr), "l"(gptr));
}
__device__ __forceinline__ void cp_commit() {
    asm volatile("cp.async.commit_group;");
}
template<int N>
__device__ __forceinline__ void cp_wait() {
    asm volatile("cp.async.wait_group %0;" :: "n"(N));
}
// SMEM -> GMEM bulk copy (copy engine; no per-thread STG issue cost)
__device__ __forceinline__ void bulk_s2g(void* gptr, uint32_t saddr, int bytes) {
    asm volatile("cp.async.bulk.global.shared::cta.bulk_group [%0], [%1], %2;"
                 :: "l"(gptr), "r"(saddr), "r"(bytes) : "memory");
}
__device__ __forceinline__ void bulk_commit() {
    asm volatile("cp.async.bulk.commit_group;");
}
__device__ __forceinline__ void bulk_wait0() {
    asm volatile("cp.async.bulk.wait_group 0;" ::: "memory");
}

// Fully-unrolled top-8 insertion (registers only; sorted descending)
__device__ __forceinline__ void top8_insert(float (&tv)[8], int (&ti)[8], float v, int n) {
    if (v > tv[7]) {
#pragma unroll
        for (int s = 0; s < 8; ++s) {
            if (v > tv[s]) {
                float a = tv[s]; int b = ti[s];
                tv[s] = v; ti[s] = n;
                v = a; n = b;
            }
        }
    }
}

// ---------------------------------------------------------------------------
// SMEM layout: [0, 64KB) 8 warps x 2 x 4KB double buffers (merge reuses the
// low part), [64KB, 72KB) dedicated zero buffer for the bulk-copy fill.
// ---------------------------------------------------------------------------
#define SMEM_BYTES 73728
#define ZBUF_FLOAT_OFF 16384   // 64KB / 4

struct FillState {
    char*    gbase;     // output byte base
    long     cbeg;      // first chunk (global index)
    long     cend;      // one past last chunk
    uint32_t zbuf;      // smem address of zero buffer
};

__device__ __forceinline__ void fill_tick(const FillState& F, int tick, int tid) {
    if (tid != 0) return;
    long a = F.cbeg + (long)tick * CH_PER_TICK;
    long b = a + CH_PER_TICK; if (b > F.cend) b = F.cend;
    if (a >= b) return;
    for (long c = a; c < b; c++)
        bulk_s2g(F.gbase + c * CHUNK, F.zbuf, (int)CHUNK);
    bulk_commit();
}

// ---------------------------------------------------------------------------
// One attention stage: stream N rows of X in 128-row tiles (per-warp cp.async
// double-buffered 16-row slices), per-lane top-8 over logits pk . X[n],
// block merge -> softmax -> weighted gather into outb.
// ---------------------------------------------------------------------------
template<int NT>   // N / 128 tiles
__device__ __forceinline__ void topk_stage(
    const float* __restrict__ Xb, float* __restrict__ outb,
    const unsigned long long (&pk)[32],
    float* smem, int tid, int lane, int warp, int pBase,
    const FillState& F, int tickBase)
{
    const uint32_t wbufB = smem_u32(smem) + warp * 8192;
    float* wbufF = smem + warp * 2048;

    float topv[8]; int topi[8];
#pragma unroll
    for (int s = 0; s < 8; s++) { topv[s] = -INFINITY; topi[s] = 0; }

    // Stage warp slice (16 rows = 4KB) of tile t into buffer (t&1)
    auto stage = [&](int t) {
        const float4* g = (const float4*)Xb + ((size_t)t * 128 + warp * 16) * 16;
        uint32_t dst = wbufB + (t & 1) * 4096;
#pragma unroll
        for (int i = 0; i < 8; i++)
            cp_async16(dst + 16 * (lane + 32 * i), g + lane + 32 * i);
        cp_commit();
    };

    stage(0);

    for (int tile = 0; tile < NT; tile++) {
        if (tile + 1 < NT) { stage(tile + 1); cp_wait<1>(); }
        else               { cp_wait<0>(); }
        __syncwarp();

        // Paced zero-fill issuance (copy engine drains under compute)
        fill_tick(F, tickBase + tile, tid);

        const float* buf = wbufF + (tile & 1) * 1024;
        const ulonglong2* xrow = (const ulonglong2*)buf;
        const int nbase = tile * 128 + warp * 16;
#pragma unroll 2
        for (int r = 0; r < 16; r += 2) {
            unsigned long long a0 = 0ull, a1 = 0ull, b0 = 0ull, b1 = 0ull;
            const ulonglong2* xr0 = xrow + r * 16;
            const ulonglong2* xr1 = xr0 + 16;
#pragma unroll
            for (int k8 = 0; k8 < 16; k8++) {
                ulonglong2 x0 = xr0[k8];
                ulonglong2 x1 = xr1[k8];
                ffma2(a0, pk[2 * k8],     x0.x);
                ffma2(a1, pk[2 * k8 + 1], x0.y);
                ffma2(b0, pk[2 * k8],     x1.x);
                ffma2(b1, pk[2 * k8 + 1], x1.y);
            }
            float v0 = pairsum(a0) + pairsum(a1);
            float v1 = pairsum(b0) + pairsum(b1);
            top8_insert(topv, topi, v0, nbase + r);
            top8_insert(topv, topi, v1, nbase + r + 1);
        }
        __syncwarp();
    }

    // ---- merge phase (reuses low smem; zero buffer at 64KB untouched) ----
    __syncthreads();
    float* candV = smem;                         // [32][65] padded
    int*   candI = (int*)(smem + 32 * 65);       // [32][65]
    float* wV    = smem + 2 * 32 * 65;           // [32][8]
    int*   wI    = (int*)(smem + 2 * 32 * 65 + 32 * 8);

#pragma unroll
    for (int s = 0; s < 8; s++) {
        candV[lane * 65 + warp * 8 + s] = topv[s];
        candI[lane * 65 + warp * 8 + s] = topi[s];
    }
    __syncthreads();

    if (tid < 32) {
        int m = tid;
        float fv[8]; int fi[8];
#pragma unroll
        for (int s = 0; s < 8; s++) { fv[s] = -INFINITY; fi[s] = 0; }
        for (int c = 0; c < 64; c++)
            top8_insert(fv, fi, candV[m * 65 + c], candI[m * 65 + c]);
        float w[8]; float sum = 0.f;
#pragma unroll
        for (int s = 0; s < 8; s++) { w[s] = expf(fv[s] - fv[0]); sum += w[s]; }
        float inv = 1.f / sum;
#pragma unroll
        for (int s = 0; s < 8; s++) { wV[m * 8 + s] = w[s] * inv; wI[m * 8 + s] = fi[s]; }
    }
    __syncthreads();

    // Weighted gather: out[p][d] = sum_k w_k * X[idx_k][d]  (rows are L2-hot)
#pragma unroll
    for (int i = 0; i < 8; i++) {
        int lin = tid + 256 * i;
        int m = lin >> 6, d = lin & 63;
        float s = 0.f;
#pragma unroll
        for (int kk = 0; kk < 8; kk++)
            s += wV[m * 8 + kk] * Xb[(size_t)wI[m * 8 + kk] * 64 + d];
        outb[(size_t)(pBase + m) * 64 + d] = s;
    }
    __syncthreads();   // protect wV/wI before smem is re-staged by next stage
}

// ---------------------------------------------------------------------------
// Fused kernel: pillar registers loaded ONCE; memory stage (W, 4 tiles) then
// points stage (32 tiles); paced bulk-copy zero-fill runs throughout.
// ---------------------------------------------------------------------------
__global__ __launch_bounds__(256, 2) void fused_topk_kernel(
    const float* __restrict__ pillars,  // [B, P, 64]
    const float* __restrict__ points,   // [B, NP, 64]
    const float* __restrict__ W,        // [M, 64]
    float* __restrict__ outPosP,        // [B, P, 64]
    float* __restrict__ outPosM,        // [B, P, 64]
    float* __restrict__ fillBase)       // d_out base (spatial region)
{
    extern __shared__ float smem[];

    const int b = blockIdx.y;
    const int pBase = blockIdx.x * 32;
    const float* pil = pillars + (size_t)b * Pq * 64;

    const int tid  = threadIdx.x;
    const int lane = tid & 31;
    const int warp = tid >> 5;

    // Init the 8KB zero buffer for bulk-copy fill (written once, read by the
    // async proxy for the whole kernel).
    {
        float4* z = (float4*)(smem + ZBUF_FLOAT_OFF);
        z[tid]       = make_float4(0.f, 0.f, 0.f, 0.f);
        z[tid + 256] = make_float4(0.f, 0.f, 0.f, 0.f);
        asm volatile("fence.proxy.async.shared::cta;" ::: "memory");
    }

    // Lane-private pillar row in registers as 32 f32x2 pairs
    unsigned long long pk[32];
    {
        const float4* prow = (const float4*)(pil + (size_t)(pBase + lane) * 64);
#pragma unroll
        for (int i = 0; i < 16; i++) {
            float4 f = prow[i];
            pk[2 * i]     = pack2(f.x, f.y);
            pk[2 * i + 1] = pack2(f.z, f.w);
        }
    }
    __syncthreads();   // zero buffer visible before any bulk issuance

    // Per-block fill chunk range
    FillState F;
    {
        long blin = (long)b * gridDim.x + blockIdx.x;
        F.gbase = (char*)fillBase;
        F.cbeg  = blin * CH_PER_BLK;
        F.cend  = F.cbeg + CH_PER_BLK; if (F.cend > NCHUNKS) F.cend = NCHUNKS;
        F.zbuf  = smem_u32(smem + ZBUF_FLOAT_OFF);
    }

    // Stage 1: memory unit (W, shared across batches), ticks 0..3
    topk_stage<Mq / 128>(W, outPosM + (size_t)b * Pq * 64, pk, smem,
                         tid, lane, warp, pBase, F, 0);

    // Stage 2: point attention, ticks 4..35
    topk_stage<NPq / 128>(points + (size_t)b * NPq * 64,
                          outPosP + (size_t)b * Pq * 64, pk, smem,
                          tid, lane, warp, pBase, F, Mq / 128);

    // Ensure all bulk-copy zero stores are globally visible before exit.
    if (tid == 0) bulk_wait0();
}

// ---------------------------------------------------------------------------
// Scatter: winner pillar per BEV column writes the three dense grids.
// ---------------------------------------------------------------------------
__global__ __launch_bounds__(64) void scatter_kernel(
    const float* __restrict__ pillars, const float* __restrict__ scales,
    const float* __restrict__ posP,    const float* __restrict__ posM,
    const int* __restrict__ idxs,      float* __restrict__ out)
{
    int bp = blockIdx.x;
    int b = bp / Pq, p = bp - b * Pq;
    int col = idxs[bp];
    if (g_winner[b * HWq + col] != p) return;
    int d = threadIdx.x;

    size_t o = (size_t)bp * 64 + d;
    float pilv = pillars[o];
    float scv  = scales[o];
    float ppv  = posP[o];
    float pmv  = posM[o];

    float* sp  = out;               // spatial_features       [B,128,HW]: [pillars ; pos_mem]
    float* spp = out + (size_t)O1;  // spatial_features_point [B,128,HW]: [pillars ; pos_point]
    float* sps = out + (size_t)O2;  // spatial_scale_features [B, 64,HW]

    size_t base = (size_t)b * 128 * HWq + (size_t)d * HWq + col;
    sp [base] = pilv;
    sp [base + (size_t)64 * HWq] = pmv;
    spp[base] = pilv;
    spp[base + (size_t)64 * HWq] = ppv;
    sps[(size_t)b * 64 * HWq + (size_t)d * HWq + col] = scv;
}

// ---------------------------------------------------------------------------
extern "C" void kernel_launch(void* const* d_in, const int* in_sizes, int n_in,
                              void* d_out, int out_size) {
    (void)in_sizes; (void)n_in; (void)out_size;
    const float* pillars = (const float*)d_in[0];   // [B,P,64]
    const float* scales  = (const float*)d_in[1];   // [B,P,64]
    const float* points  = (const float*)d_in[2];   // [B,NP,64]
    const float* W       = (const float*)d_in[3];   // [M,64]
    const int*   idxs    = (const int*)d_in[4];     // [B,P]
    float* out = (float*)d_out;

    cudaFuncSetAttribute(fused_topk_kernel,
                         cudaFuncAttributeMaxDynamicSharedMemorySize, SMEM_BYTES);

    winner_reset_kernel<<<(Bq * HWq + 255) / 256, 256>>>();
    winner_mark_kernel<<<(Bq * Pq + 255) / 256, 256>>>(idxs);

    dim3 grid(Pq / 32, Bq);   // 125 x 2 = 250 blocks
    fused_topk_kernel<<<grid, 256, SMEM_BYTES>>>(
        pillars, points, W, out + O3, out + O4, out);

    scatter_kernel<<<Bq * Pq, 64>>>(pillars, scales, out + O3, out + O4, idxs, out);
}